// round 1
// baseline (speedup 1.0000x reference)
#include <cuda_runtime.h>
#include <math.h>

#define HW 16384   // 128*128

// ---------------- scratch (device globals; no allocation allowed) ----------
static __device__ float g_out1[2*25*8*HW];   // conv00 output [n][c25][d][hw]
static __device__ float g_z[2*8*HW];         // conv0 output  [n][d][hw]
static __device__ float g_y[8*2*25*HW];      // conv1^2 out   [t][n][c][hw]
static __device__ float g_h  [2*25*HW];
static __device__ float g_hg [2*25*HW];
static __device__ float g_ns1[2*25*HW];
static __device__ float g_c1 [2*25*HW];
static __device__ float g_c2 [2*25*HW];
static __device__ float g_mean[3][25];
static __device__ float g_rstd[3][25];
static __device__ float g_part[128*2];

__device__ __forceinline__ float softplusf(float x) {
    // matches jax.nn.softplus = max(x,0) + log1p(exp(-|x|))
    return fmaxf(x, 0.f) + log1pf(expf(-fabsf(x)));
}
__device__ __forceinline__ float sigmoidf_(float x) {
    return 1.f / (1.f + expf(-x));
}

// ---------------------------------------------------------------------------
// conv00: x[2,3,8,128,128] (*) w[25,3,7,7,7], pad 3 -> g_out1
// block: 256 thr, tile 32x16, thread = 2 x-px, all 25 out channels
// grid (4, 8, 16) ; z = n*8 + d
// ---------------------------------------------------------------------------
__global__ __launch_bounds__(256) void k_conv00(const float* __restrict__ x,
                                                const float* __restrict__ w) {
    const int n = blockIdx.z >> 3, d = blockIdx.z & 7;
    const int x0 = blockIdx.x * 32, y0 = blockIdx.y * 16;
    const int tx = threadIdx.x & 15, ty = threadIdx.x >> 4;

    __shared__ float s_in[22 * 40];
    __shared__ __align__(16) float s_w[49 * 28];

    float acc[25][2];
#pragma unroll
    for (int c = 0; c < 25; c++) { acc[c][0] = 0.f; acc[c][1] = 0.f; }

    const int id_lo = (d - 3 < 0) ? 0 : d - 3;
    const int id_hi = (d + 3 > 7) ? 7 : d + 3;

    for (int ci = 0; ci < 3; ci++) {
        for (int id = id_lo; id <= id_hi; id++) {
            const int kd = id - d + 3;
            __syncthreads();
            const float* src = x + (size_t)((n * 3 + ci) * 8 + id) * HW;
            for (int t = threadIdx.x; t < 22 * 38; t += 256) {
                int r = t / 38, c2 = t % 38;
                int gy = y0 - 3 + r, gx = x0 - 3 + c2;
                float v = 0.f;
                if ((unsigned)gy < 128u && (unsigned)gx < 128u) v = src[gy * 128 + gx];
                s_in[r * 40 + c2] = v;
            }
            for (int t = threadIdx.x; t < 49 * 25; t += 256) {
                int tap = t / 25, oc = t % 25;
                s_w[tap * 28 + oc] = w[((oc * 3 + ci) * 7 + kd) * 49 + tap];
            }
            __syncthreads();
#pragma unroll 1
            for (int ky = 0; ky < 7; ky++) {
#pragma unroll
                for (int kx = 0; kx < 7; kx++) {
                    float a0 = s_in[(ty + ky) * 40 + tx * 2 + kx];
                    float a1 = s_in[(ty + ky) * 40 + tx * 2 + kx + 1];
                    const float4* W = (const float4*)&s_w[(ky * 7 + kx) * 28];
                    float wv[28];
#pragma unroll
                    for (int q = 0; q < 7; q++) {
                        float4 f = W[q];
                        wv[4*q] = f.x; wv[4*q+1] = f.y; wv[4*q+2] = f.z; wv[4*q+3] = f.w;
                    }
#pragma unroll
                    for (int oc = 0; oc < 25; oc++) {
                        acc[oc][0] = fmaf(a0, wv[oc], acc[oc][0]);
                        acc[oc][1] = fmaf(a1, wv[oc], acc[oc][1]);
                    }
                }
            }
        }
    }
    const int yy = y0 + ty, xx = x0 + tx * 2;
#pragma unroll
    for (int oc = 0; oc < 25; oc++) {
        float* dst = g_out1 + (size_t)((n * 25 + oc) * 8 + d) * HW + yy * 128 + xx;
        dst[0] = acc[oc][0];
        dst[1] = acc[oc][1];
    }
}

// ---------------------------------------------------------------------------
// conv0: g_out1[2,25,8,...] (*) w[1,25,7,7,7], pad 3 -> g_z [2,8,...]
// block 256 thr, tile 64x16, thread = 4 x-px ; grid (2, 8, 16)
// ---------------------------------------------------------------------------
__global__ __launch_bounds__(256) void k_conv0(const float* __restrict__ w) {
    const int n = blockIdx.z >> 3, d = blockIdx.z & 7;
    const int x0 = blockIdx.x * 64, y0 = blockIdx.y * 16;
    const int tx = threadIdx.x & 15, ty = threadIdx.x >> 4;

    __shared__ __align__(16) float s_in[22 * 72];
    __shared__ __align__(16) float s_w[7 * 8];

    float acc[4] = {0.f, 0.f, 0.f, 0.f};

    const int id_lo = (d - 3 < 0) ? 0 : d - 3;
    const int id_hi = (d + 3 > 7) ? 7 : d + 3;

    for (int mid = 0; mid < 25; mid++) {
        for (int id = id_lo; id <= id_hi; id++) {
            const int kd = id - d + 3;
            __syncthreads();
            const float* src = g_out1 + (size_t)((n * 25 + mid) * 8 + id) * HW;
            for (int t = threadIdx.x; t < 22 * 70; t += 256) {
                int r = t / 70, c2 = t % 70;
                int gy = y0 - 3 + r, gx = x0 - 3 + c2;
                float v = 0.f;
                if ((unsigned)gy < 128u && (unsigned)gx < 128u) v = src[gy * 128 + gx];
                s_in[r * 72 + c2] = v;
            }
            for (int t = threadIdx.x; t < 49; t += 256) {
                s_w[(t / 7) * 8 + (t % 7)] = w[(mid * 7 + kd) * 49 + t];
            }
            __syncthreads();
#pragma unroll 1
            for (int ky = 0; ky < 7; ky++) {
                const int base = (ty + ky) * 72 + tx * 4;
                float r[12];
                float4 a = *(const float4*)&s_in[base];
                float4 b = *(const float4*)&s_in[base + 4];
                float4 c = *(const float4*)&s_in[base + 8];
                r[0]=a.x; r[1]=a.y; r[2]=a.z; r[3]=a.w;
                r[4]=b.x; r[5]=b.y; r[6]=b.z; r[7]=b.w;
                r[8]=c.x; r[9]=c.y; r[10]=c.z; r[11]=c.w;
                float4 w0 = *(const float4*)&s_w[ky * 8];
                float4 w1 = *(const float4*)&s_w[ky * 8 + 4];
                float wv[8] = {w0.x, w0.y, w0.z, w0.w, w1.x, w1.y, w1.z, w1.w};
#pragma unroll
                for (int kx = 0; kx < 7; kx++) {
#pragma unroll
                    for (int j = 0; j < 4; j++)
                        acc[j] = fmaf(r[kx + j], wv[kx], acc[j]);
                }
            }
        }
    }
    float* dst = g_z + (size_t)(n * 8 + d) * HW + (y0 + ty) * 128 + x0 + tx * 4;
#pragma unroll
    for (int j = 0; j < 4; j++) dst[j] = acc[j];
}

// ---------------------------------------------------------------------------
// conv1 + bias + square: g_z (*) w[25,1,7,7,7] pad 3, +b, ^2 -> g_y[t][n][c]
// same structure as conv00 without ci loop ; grid (4, 8, 16)
// ---------------------------------------------------------------------------
__global__ __launch_bounds__(256) void k_conv1sq(const float* __restrict__ w,
                                                 const float* __restrict__ bias) {
    const int n = blockIdx.z >> 3, d = blockIdx.z & 7;
    const int x0 = blockIdx.x * 32, y0 = blockIdx.y * 16;
    const int tx = threadIdx.x & 15, ty = threadIdx.x >> 4;

    __shared__ float s_in[22 * 40];
    __shared__ __align__(16) float s_w[49 * 28];

    float acc[25][2];
#pragma unroll
    for (int c = 0; c < 25; c++) { acc[c][0] = 0.f; acc[c][1] = 0.f; }

    const int id_lo = (d - 3 < 0) ? 0 : d - 3;
    const int id_hi = (d + 3 > 7) ? 7 : d + 3;

    for (int id = id_lo; id <= id_hi; id++) {
        const int kd = id - d + 3;
        __syncthreads();
        const float* src = g_z + (size_t)(n * 8 + id) * HW;
        for (int t = threadIdx.x; t < 22 * 38; t += 256) {
            int r = t / 38, c2 = t % 38;
            int gy = y0 - 3 + r, gx = x0 - 3 + c2;
            float v = 0.f;
            if ((unsigned)gy < 128u && (unsigned)gx < 128u) v = src[gy * 128 + gx];
            s_in[r * 40 + c2] = v;
        }
        for (int t = threadIdx.x; t < 49 * 25; t += 256) {
            int tap = t / 25, oc = t % 25;
            s_w[tap * 28 + oc] = w[(oc * 7 + kd) * 49 + tap];
        }
        __syncthreads();
#pragma unroll 1
        for (int ky = 0; ky < 7; ky++) {
#pragma unroll
            for (int kx = 0; kx < 7; kx++) {
                float a0 = s_in[(ty + ky) * 40 + tx * 2 + kx];
                float a1 = s_in[(ty + ky) * 40 + tx * 2 + kx + 1];
                const float4* W = (const float4*)&s_w[(ky * 7 + kx) * 28];
                float wv[28];
#pragma unroll
                for (int q = 0; q < 7; q++) {
                    float4 f = W[q];
                    wv[4*q] = f.x; wv[4*q+1] = f.y; wv[4*q+2] = f.z; wv[4*q+3] = f.w;
                }
#pragma unroll
                for (int oc = 0; oc < 25; oc++) {
                    acc[oc][0] = fmaf(a0, wv[oc], acc[oc][0]);
                    acc[oc][1] = fmaf(a1, wv[oc], acc[oc][1]);
                }
            }
        }
    }
    const int yy = y0 + ty, xx = x0 + tx * 2;
#pragma unroll
    for (int oc = 0; oc < 25; oc++) {
        float b = bias[oc];
        float v0 = acc[oc][0] + b;
        float v1 = acc[oc][1] + b;
        // g_y layout: [t=d][n][oc][hw]
        float* dst = g_y + (size_t)((d * 2 + n) * 25 + oc) * HW + yy * 128 + xx;
        dst[0] = v0 * v0;
        dst[1] = v1 * v1;
    }
}

// ---------------------------------------------------------------------------
// conv15: [2,25,128,128] (*) w[25,25,15,15] pad 7 -> out
// phase 0: in=g_hg out=g_c1 ; phase 1: in=g_ns1 out=g_c2
// block 128 thr (tx<16 -> 2 x-px, ty<8), tile 32x8, 5 out-ch per block
// grid (4, 16, 10) ; z = n*5 + ocg
// ---------------------------------------------------------------------------
__global__ __launch_bounds__(128) void k_conv15(const float* __restrict__ w, int phase) {
    const float* __restrict__ in  = phase ? g_ns1 : g_hg;
    float* __restrict__       out = phase ? g_c2  : g_c1;

    const int n = blockIdx.z / 5, ocb = (blockIdx.z % 5) * 5;
    const int x0 = blockIdx.x * 32, y0 = blockIdx.y * 8;
    const int tx = threadIdx.x & 15, ty = threadIdx.x >> 4;

    __shared__ __align__(16) float s_in[22 * 48];
    __shared__ __align__(16) float s_w[5 * 15 * 16];  // [oc][ky][16]

    float acc[5][2];
#pragma unroll
    for (int c = 0; c < 5; c++) { acc[c][0] = 0.f; acc[c][1] = 0.f; }

    for (int cin = 0; cin < 25; cin++) {
        __syncthreads();
        const float* src = in + (size_t)(n * 25 + cin) * HW;
        for (int t = threadIdx.x; t < 22 * 46; t += 128) {
            int r = t / 46, c2 = t % 46;
            int gy = y0 - 7 + r, gx = x0 - 7 + c2;
            float v = 0.f;
            if ((unsigned)gy < 128u && (unsigned)gx < 128u) v = src[gy * 128 + gx];
            s_in[r * 48 + c2] = v;
        }
        for (int t = threadIdx.x; t < 5 * 225; t += 128) {
            int oc = t / 225, rem = t % 225;
            s_w[oc * 240 + (rem / 15) * 16 + (rem % 15)] =
                w[((size_t)(ocb + oc) * 25 + cin) * 225 + rem];
        }
        __syncthreads();
#pragma unroll 1
        for (int ky = 0; ky < 15; ky++) {
            const int base = (ty + ky) * 48 + tx * 2;
            float r[16];
#pragma unroll
            for (int q = 0; q < 8; q++) {
                float2 f = *(const float2*)&s_in[base + 2 * q];
                r[2*q] = f.x; r[2*q+1] = f.y;
            }
#pragma unroll
            for (int oc = 0; oc < 5; oc++) {
                const float4* W = (const float4*)&s_w[oc * 240 + ky * 16];
                float wv[16];
#pragma unroll
                for (int q = 0; q < 4; q++) {
                    float4 f = W[q];
                    wv[4*q] = f.x; wv[4*q+1] = f.y; wv[4*q+2] = f.z; wv[4*q+3] = f.w;
                }
#pragma unroll
                for (int kx = 0; kx < 15; kx++) {
                    acc[oc][0] = fmaf(r[kx],     wv[kx], acc[oc][0]);
                    acc[oc][1] = fmaf(r[kx + 1], wv[kx], acc[oc][1]);
                }
            }
        }
    }
    const int yy = y0 + ty, xx = x0 + tx * 2;
#pragma unroll
    for (int oc = 0; oc < 5; oc++) {
        float* dst = out + (size_t)(n * 25 + ocb + oc) * HW + yy * 128 + xx;
        dst[0] = acc[oc][0];
        dst[1] = acc[oc][1];
    }
}

// ---------------------------------------------------------------------------
// BN batch statistics over (N,H,W) per channel. phase 0: g_c1, 1: g_c2, 2: g_h
// 25 blocks x 256 threads; deterministic tree reduction.
// ---------------------------------------------------------------------------
__global__ void k_bnstats(int phase) {
    const float* src = (phase == 0) ? g_c1 : (phase == 1) ? g_c2 : g_h;
    const int c = blockIdx.x;
    float s = 0.f, q = 0.f;
    for (int j = threadIdx.x; j < 32768; j += 256) {
        int n = j >> 14, p = j & 16383;
        float v = src[(size_t)(n * 25 + c) * HW + p];
        s += v;
        q = fmaf(v, v, q);
    }
    __shared__ float ss[256], sq[256];
    ss[threadIdx.x] = s; sq[threadIdx.x] = q;
    __syncthreads();
    for (int o = 128; o > 0; o >>= 1) {
        if (threadIdx.x < o) {
            ss[threadIdx.x] += ss[threadIdx.x + o];
            sq[threadIdx.x] += sq[threadIdx.x + o];
        }
        __syncthreads();
    }
    if (threadIdx.x == 0) {
        float m = ss[0] * (1.f / 32768.f);
        float var = sq[0] * (1.f / 32768.f) - m * m;
        g_mean[phase][c] = m;
        g_rstd[phase][c] = rsqrtf(var + 1e-3f);
    }
}

// ---------------------------------------------------------------------------
// g1 gate + multiply: g_hg = h * sigmoid(1x1(h) + u1_b). 128 blocks x 256.
// ---------------------------------------------------------------------------
__global__ void k_g1(const float* __restrict__ u1w, const float* __restrict__ u1b) {
    __shared__ float sw[625];
    __shared__ float sb[25];
    for (int t = threadIdx.x; t < 625; t += 256) sw[t] = u1w[t];
    if (threadIdx.x < 25) sb[threadIdx.x] = u1b[threadIdx.x];
    __syncthreads();

    const int gid = blockIdx.x * 256 + threadIdx.x;  // 0..32767
    const int n = gid >> 14, p = gid & 16383;
    float hv[25];
#pragma unroll
    for (int i = 0; i < 25; i++) hv[i] = g_h[(size_t)(n * 25 + i) * HW + p];
#pragma unroll
    for (int c = 0; c < 25; c++) {
        float dot = sb[c];
#pragma unroll
        for (int i = 0; i < 25; i++) dot = fmaf(sw[c * 25 + i], hv[i], dot);
        float g = sigmoidf_(dot);
        g_hg[(size_t)(n * 25 + c) * HW + p] = hv[c] * g;
    }
}

// ---------------------------------------------------------------------------
// ns1 = sp(y - sp(bn(c1) * (alpha*h + mu)))   -- elementwise. 3200 x 256.
// ---------------------------------------------------------------------------
__global__ void k_ns1(int t, const float* __restrict__ alpha, const float* __restrict__ mu,
                      const float* __restrict__ bn1w, const float* __restrict__ bn1b) {
    const int idx = blockIdx.x * 256 + threadIdx.x;
    if (idx >= 2 * 25 * HW) return;
    const int c = (idx >> 14) % 25;
    float c1 = (g_c1[idx] - g_mean[0][c]) * g_rstd[0][c] * bn1w[c] + bn1b[c];
    float h = g_h[idx];
    float y = g_y[(size_t)t * (2 * 25 * HW) + idx];
    float inner = softplusf(c1 * fmaf(alpha[c], h, mu[c]));
    g_ns1[idx] = softplusf(y - inner);
}

// ---------------------------------------------------------------------------
// h update: g2 = sigmoid(1x1(ns1)+u2_b); c2n = bn(c2);
// h2 = sp(kappa*ns1 + gamma*c2n + wmix*ns1*c2n); h = sp((1-g2)*h + g2*h2)
// 128 blocks x 256.
// ---------------------------------------------------------------------------
__global__ void k_hnew(const float* __restrict__ u2w, const float* __restrict__ u2b,
                       const float* __restrict__ kappa, const float* __restrict__ gammap,
                       const float* __restrict__ wmix,
                       const float* __restrict__ bn3w, const float* __restrict__ bn3b) {
    __shared__ float sw[625];
    __shared__ float sb[25], sk[25], sg[25], sm[25], s3w[25], s3b[25];
    for (int t = threadIdx.x; t < 625; t += 256) sw[t] = u2w[t];
    if (threadIdx.x < 25) {
        sb[threadIdx.x]  = u2b[threadIdx.x];
        sk[threadIdx.x]  = kappa[threadIdx.x];
        sg[threadIdx.x]  = gammap[threadIdx.x];
        sm[threadIdx.x]  = wmix[threadIdx.x];
        s3w[threadIdx.x] = bn3w[threadIdx.x];
        s3b[threadIdx.x] = bn3b[threadIdx.x];
    }
    __syncthreads();

    const int gid = blockIdx.x * 256 + threadIdx.x;
    const int n = gid >> 14, p = gid & 16383;
    float nv[25];
#pragma unroll
    for (int i = 0; i < 25; i++) nv[i] = g_ns1[(size_t)(n * 25 + i) * HW + p];
#pragma unroll
    for (int c = 0; c < 25; c++) {
        float dot = sb[c];
#pragma unroll
        for (int i = 0; i < 25; i++) dot = fmaf(sw[c * 25 + i], nv[i], dot);
        float g2 = sigmoidf_(dot);
        size_t a = (size_t)(n * 25 + c) * HW + p;
        float c2n = (g_c2[a] - g_mean[1][c]) * g_rstd[1][c] * s3w[c] + s3b[c];
        float h2 = softplusf(sk[c] * nv[c] + sg[c] * c2n + sm[c] * nv[c] * c2n);
        float hold = g_h[a];
        g_h[a] = softplusf((1.f - g2) * hold + g2 * h2);
    }
}

// ---------------------------------------------------------------------------
// zero h
// ---------------------------------------------------------------------------
__global__ void k_zero() {
    int idx = blockIdx.x * 256 + threadIdx.x;
    if (idx < 2 * 25 * HW) g_h[idx] = 0.f;
}

// ---------------------------------------------------------------------------
// Epilogue: bn_out(h) -> avgpool2 -> dot with fc4 rows (stage 1, partials)
// 128 blocks x 256.
// ---------------------------------------------------------------------------
__global__ void k_pool(const float* __restrict__ bnow, const float* __restrict__ bnob,
                       const float* __restrict__ fcw) {
    const int gid = blockIdx.x * 256 + threadIdx.x;
    float p0 = 0.f, p1 = 0.f;
    for (int m = gid; m < 204800; m += 32768) {
        int n = m / 102400;
        int r = m % 102400;
        int c = r >> 12;
        int q = r & 4095;
        int i = q >> 6, j = q & 63;
        size_t base = (size_t)(n * 25 + c) * HW + (size_t)(i * 2) * 128 + j * 2;
        float s4 = g_h[base] + g_h[base + 1] + g_h[base + 128] + g_h[base + 129];
        float val = (0.25f * s4 - g_mean[2][c]) * g_rstd[2][c] * bnow[c] + bnob[c];
        p0 = fmaf(val, fcw[m], p0);
        p1 = fmaf(val, fcw[204800 + m], p1);
    }
    __shared__ float s0[256], s1[256];
    s0[threadIdx.x] = p0; s1[threadIdx.x] = p1;
    __syncthreads();
    for (int o = 128; o > 0; o >>= 1) {
        if (threadIdx.x < o) {
            s0[threadIdx.x] += s0[threadIdx.x + o];
            s1[threadIdx.x] += s1[threadIdx.x + o];
        }
        __syncthreads();
    }
    if (threadIdx.x == 0) {
        g_part[blockIdx.x * 2]     = s0[0];
        g_part[blockIdx.x * 2 + 1] = s1[0];
    }
}

__global__ void k_final(const float* __restrict__ fcb, float* __restrict__ out) {
    __shared__ float s0[128], s1[128];
    s0[threadIdx.x] = g_part[threadIdx.x * 2];
    s1[threadIdx.x] = g_part[threadIdx.x * 2 + 1];
    __syncthreads();
    for (int o = 64; o > 0; o >>= 1) {
        if (threadIdx.x < o) {
            s0[threadIdx.x] += s0[threadIdx.x + o];
            s1[threadIdx.x] += s1[threadIdx.x + o];
        }
        __syncthreads();
    }
    if (threadIdx.x == 0) {
        out[0] = sigmoidf_(s0[0] + fcb[0]);
        out[1] = sigmoidf_(s1[0] + fcb[1]);
    }
}

// ---------------------------------------------------------------------------
extern "C" void kernel_launch(void* const* d_in, const int* in_sizes, int n_in,
                              void* d_out, int out_size) {
    const float* x        = (const float*)d_in[0];
    const float* conv00_w = (const float*)d_in[1];
    const float* conv0_w  = (const float*)d_in[2];
    const float* conv1_w  = (const float*)d_in[3];
    const float* conv1_b  = (const float*)d_in[4];
    const float* u1_w     = (const float*)d_in[5];
    const float* u1_b     = (const float*)d_in[6];
    const float* u2_w     = (const float*)d_in[7];
    const float* u2_b     = (const float*)d_in[8];
    const float* w_inh    = (const float*)d_in[9];
    const float* w_exc    = (const float*)d_in[10];
    const float* alpha    = (const float*)d_in[11];
    const float* mu       = (const float*)d_in[12];
    const float* gamma_p  = (const float*)d_in[13];
    const float* kappa    = (const float*)d_in[14];
    const float* w_mix    = (const float*)d_in[15];
    const float* bn1_w    = (const float*)d_in[16];
    const float* bn1_b    = (const float*)d_in[17];
    const float* bn3_w    = (const float*)d_in[18];
    const float* bn3_b    = (const float*)d_in[19];
    const float* bn_out_w = (const float*)d_in[20];
    const float* bn_out_b = (const float*)d_in[21];
    const float* fc4_w    = (const float*)d_in[22];
    const float* fc4_b    = (const float*)d_in[23];
    float* out = (float*)d_out;

    // ---- 3D conv front-end ----
    k_conv00<<<dim3(4, 8, 16), 256>>>(x, conv00_w);
    k_conv0 <<<dim3(2, 8, 16), 256>>>(conv0_w);
    k_conv1sq<<<dim3(4, 8, 16), 256>>>(conv1_w, conv1_b);

    // ---- recurrent scan, T = 8 ----
    k_zero<<<3200, 256>>>();
    for (int t = 0; t < 8; t++) {
        k_g1<<<128, 256>>>(u1_w, u1_b);
        k_conv15<<<dim3(4, 16, 10), 128>>>(w_inh, 0);
        k_bnstats<<<25, 256>>>(0);
        k_ns1<<<3200, 256>>>(t, alpha, mu, bn1_w, bn1_b);
        k_conv15<<<dim3(4, 16, 10), 128>>>(w_exc, 1);
        k_bnstats<<<25, 256>>>(1);
        k_hnew<<<128, 256>>>(u2_w, u2_b, kappa, gamma_p, w_mix, bn3_w, bn3_b);
    }

    // ---- epilogue: bn_out -> avgpool2 -> fc -> sigmoid ----
    k_bnstats<<<25, 256>>>(2);
    k_pool<<<128, 256>>>(bn_out_w, bn_out_b, fc4_w);
    k_final<<<1, 128>>>(fc4_b, out);
}